// round 2
// baseline (speedup 1.0000x reference)
#include <cuda_runtime.h>
#include <cstdint>

#define BATCH 256
#define FEAT_DIM 512
#define NUM_CLASSES 85742

// Scratch (device globals; no allocation allowed)
__device__ float g_row_dist[BATCH];
__device__ int   g_labels_is_i64;   // 1 if labels stored as int64, 0 if int32

// Kernel 0: detect labels dtype from bit pattern. Reads only the first 256
// int32 words, which are in-bounds for BOTH layouts (int32: 256 words;
// int64: 512 words). int64 layout (little-endian, labels < 2^17) looks like
// [label,0,label,0,...] -> all odd words zero AND even words in range.
__global__ __launch_bounds__(256) void detect_labels_kernel(const int* __restrict__ labels_i32)
{
    const int tid = threadIdx.x;
    int w = labels_i32[tid];
    // For int64 hypothesis: odd-index words must be 0, even words valid labels.
    bool ok = (tid & 1) ? (w == 0) : (w >= 0 && w < NUM_CLASSES);
    int all_ok = __syncthreads_and(ok ? 1 : 0);
    if (tid == 0) g_labels_is_i64 = all_ok;
}

// Kernel 1: one block per batch row, 128 threads, float4 loads.
__global__ __launch_bounds__(128) void row_dist_kernel(
    const float* __restrict__ x,
    const int*   __restrict__ labels_i32,
    const float* __restrict__ centers)
{
    const int row = blockIdx.x;
    const int tid = threadIdx.x;

    const int lbl = g_labels_is_i64 ? labels_i32[2 * row] : labels_i32[row];

    const float4* xr = reinterpret_cast<const float4*>(x + (size_t)row * FEAT_DIM);
    const float4* cr = reinterpret_cast<const float4*>(centers + (size_t)lbl * FEAT_DIM);

    float4 xv = xr[tid];
    float4 cv = cr[tid];

    float d0 = xv.x - cv.x;
    float d1 = xv.y - cv.y;
    float d2 = xv.z - cv.z;
    float d3 = xv.w - cv.w;
    float s = d0 * d0 + d1 * d1 + d2 * d2 + d3 * d3;

    #pragma unroll
    for (int off = 16; off > 0; off >>= 1)
        s += __shfl_xor_sync(0xFFFFFFFFu, s, off);

    __shared__ float warp_sums[4];
    if ((tid & 31) == 0) warp_sums[tid >> 5] = s;
    __syncthreads();

    if (tid == 0) {
        float dist = warp_sums[0] + warp_sums[1] + warp_sums[2] + warp_sums[3];
        dist = fminf(fmaxf(dist, 1e-12f), 1e12f);
        g_row_dist[row] = dist;
    }
}

// Kernel 2: deterministic single-block mean.
__global__ __launch_bounds__(256) void reduce_mean_kernel(float* __restrict__ out)
{
    const int tid = threadIdx.x;
    float v = g_row_dist[tid];

    #pragma unroll
    for (int off = 16; off > 0; off >>= 1)
        v += __shfl_xor_sync(0xFFFFFFFFu, v, off);

    __shared__ float warp_sums[8];
    if ((tid & 31) == 0) warp_sums[tid >> 5] = v;
    __syncthreads();

    if (tid == 0) {
        float total = 0.0f;
        #pragma unroll
        for (int i = 0; i < 8; ++i) total += warp_sums[i];
        out[0] = total * (1.0f / (float)BATCH);
    }
}

extern "C" void kernel_launch(void* const* d_in, const int* in_sizes, int n_in,
                              void* d_out, int out_size)
{
    // Identify inputs by UNIQUE element counts instead of trusting order:
    //   x: 256*512 = 131072, labels: 256, centers: 85742*512 = 43899904
    const float* x = nullptr;
    const int*   labels_i32 = nullptr;
    const float* centers = nullptr;

    for (int i = 0; i < n_in; ++i) {
        if (in_sizes[i] == BATCH * FEAT_DIM)            x = (const float*)d_in[i];
        else if (in_sizes[i] == BATCH)                  labels_i32 = (const int*)d_in[i];
        else                                            centers = (const float*)d_in[i];
    }

    float* out = (float*)d_out;

    detect_labels_kernel<<<1, 256>>>(labels_i32);
    row_dist_kernel<<<BATCH, 128>>>(x, labels_i32, centers);
    reduce_mean_kernel<<<1, 256>>>(out);
}

// round 3
// speedup vs baseline: 1.0036x; 1.0036x over previous
#include <cuda_runtime.h>
#include <cstdint>

#define BATCH 256
#define FEAT_DIM 512
#define NUM_CLASSES 85742

// Scratch (device globals zero-initialized; no allocation allowed)
__device__ float g_row_dist[BATCH];
__device__ unsigned int g_done_ctr;   // starts 0; last block resets it to 0

// Single fused kernel: dtype-detect + gather + row distance + final mean.
// 256 blocks x 128 threads, one block per batch row.
__global__ __launch_bounds__(128) void center_loss_fused_kernel(
    const float* __restrict__ x,
    const int*   __restrict__ labels_i32,
    const float* __restrict__ centers,
    float*       __restrict__ out)
{
    const int row = blockIdx.x;
    const int tid = threadIdx.x;

    // ---- Redundant per-block dtype detection (reads first 256 i32 words,
    // in-bounds for both int32[256] and int64[256] layouts).
    // int64 little-endian with labels < 2^17: words are [lbl,0,lbl,0,...].
    int w0 = labels_i32[tid];
    int w1 = labels_i32[tid + 128];
    bool ok0 = (tid & 1) ? (w0 == 0) : (w0 >= 0 && w0 < NUM_CLASSES);
    bool ok1 = (tid & 1) ? (w1 == 0) : (w1 >= 0 && w1 < NUM_CLASSES); // (tid+128) parity == tid parity
    int is_i64 = __syncthreads_and((ok0 && ok1) ? 1 : 0);

    const int lbl = is_i64 ? labels_i32[2 * row] : labels_i32[row];

    // ---- Row distance: 512 floats = 128 float4, one per thread.
    const float4* xr = reinterpret_cast<const float4*>(x + (size_t)row * FEAT_DIM);
    const float4* cr = reinterpret_cast<const float4*>(centers + (size_t)lbl * FEAT_DIM);

    float4 xv = xr[tid];
    float4 cv = cr[tid];

    float d0 = xv.x - cv.x;
    float d1 = xv.y - cv.y;
    float d2 = xv.z - cv.z;
    float d3 = xv.w - cv.w;
    float s = d0 * d0 + d1 * d1 + d2 * d2 + d3 * d3;

    #pragma unroll
    for (int off = 16; off > 0; off >>= 1)
        s += __shfl_xor_sync(0xFFFFFFFFu, s, off);

    __shared__ float warp_sums[4];
    __shared__ int s_last;
    if ((tid & 31) == 0) warp_sums[tid >> 5] = s;
    __syncthreads();

    if (tid == 0) {
        float dist = warp_sums[0] + warp_sums[1] + warp_sums[2] + warp_sums[3];
        dist = fminf(fmaxf(dist, 1e-12f), 1e12f);
        g_row_dist[row] = dist;
        __threadfence();                       // publish before arrival
        unsigned int old = atomicAdd(&g_done_ctr, 1u);
        s_last = (old == BATCH - 1) ? 1 : 0;
    }
    __syncthreads();

    // ---- Last block computes the mean deterministically (fixed order).
    if (s_last) {
        __threadfence();                       // acquire all g_row_dist writes
        float v = g_row_dist[tid] + g_row_dist[tid + 128];

        #pragma unroll
        for (int off = 16; off > 0; off >>= 1)
            v += __shfl_xor_sync(0xFFFFFFFFu, v, off);

        if ((tid & 31) == 0) warp_sums[tid >> 5] = v;
        __syncthreads();

        if (tid == 0) {
            float total = warp_sums[0] + warp_sums[1] + warp_sums[2] + warp_sums[3];
            out[0] = total * (1.0f / (float)BATCH);
            g_done_ctr = 0;                    // reset for next graph replay
        }
    }
}

extern "C" void kernel_launch(void* const* d_in, const int* in_sizes, int n_in,
                              void* d_out, int out_size)
{
    // Identify inputs by UNIQUE element counts (order-proof):
    //   x: 131072, labels: 256, centers: 43899904
    const float* x = nullptr;
    const int*   labels_i32 = nullptr;
    const float* centers = nullptr;

    for (int i = 0; i < n_in; ++i) {
        if (in_sizes[i] == BATCH * FEAT_DIM)   x = (const float*)d_in[i];
        else if (in_sizes[i] == BATCH)         labels_i32 = (const int*)d_in[i];
        else                                   centers = (const float*)d_in[i];
    }

    center_loss_fused_kernel<<<BATCH, 128>>>(x, labels_i32, centers, (float*)d_out);
}

// round 4
// speedup vs baseline: 1.3413x; 1.3365x over previous
#include <cuda_runtime.h>
#include <cstdint>

#define BATCH 256
#define FEAT_DIM 512
#define NUM_CLASSES 85742

#define FX_SCALE 16777216.0f          // 2^24 fixed-point scale
#define FX_MASK  ((1ULL << 48) - 1ULL)
#define CNT_ONE  (1ULL << 48)

// Packed accumulator: bits [48..] = arrival count, bits [0..48) = fixed-point sum.
// Zero-initialized device global; last warp resets it each launch (graph-replay safe).
__device__ unsigned long long g_acc;

// 32 blocks x 256 threads; each warp handles one batch row. No block-level syncs.
__global__ __launch_bounds__(256) void center_loss_onepass_kernel(
    const float* __restrict__ x,
    const int*   __restrict__ labels_i32,
    const float* __restrict__ centers,
    float*       __restrict__ out)
{
    const int lane = threadIdx.x & 31;
    const int warp = threadIdx.x >> 5;
    const int row  = blockIdx.x * 8 + warp;

    // ---- Warp-uniform dtype detection on words [0..63] of the labels buffer
    // (in-bounds for both int32[256] and int64[256] layouts).
    // int64 little-endian, labels < 2^17  =>  words look like [lbl,0,lbl,0,...].
    int we = labels_i32[2 * lane];       // even word: candidate label
    int wo = labels_i32[2 * lane + 1];   // odd word: must be 0 if int64
    bool ok = (wo == 0) && (we >= 0) && (we < NUM_CLASSES);
    bool is_i64 = __all_sync(0xFFFFFFFFu, ok);

    const int lbl = is_i64 ? labels_i32[2 * row] : labels_i32[row];

    // ---- Row squared distance: 128 float4 per row, 4 per lane (MLP=8).
    const float4* xr = reinterpret_cast<const float4*>(x) + (size_t)row * (FEAT_DIM / 4);
    const float4* cr = reinterpret_cast<const float4*>(centers) + (size_t)lbl * (FEAT_DIM / 4);

    float s = 0.0f;
    #pragma unroll
    for (int i = 0; i < 4; ++i) {
        float4 xv = xr[lane + 32 * i];
        float4 cv = cr[lane + 32 * i];
        float d0 = xv.x - cv.x;
        float d1 = xv.y - cv.y;
        float d2 = xv.z - cv.z;
        float d3 = xv.w - cv.w;
        s += d0 * d0 + d1 * d1 + d2 * d2 + d3 * d3;
    }

    #pragma unroll
    for (int off = 16; off > 0; off >>= 1)
        s += __shfl_xor_sync(0xFFFFFFFFu, s, off);

    if (lane == 0) {
        float dist = fminf(fmaxf(s, 1e-12f), 1e12f);
        // Deterministic accumulation: integer fixed-point, order-independent.
        unsigned long long add = CNT_ONE + __float2ull_rn(dist * FX_SCALE);
        unsigned long long old = atomicAdd(&g_acc, add);
        if ((old >> 48) == (BATCH - 1)) {
            // This warp completes the sum; it already has the total in hand.
            unsigned long long total = (old + add) & FX_MASK;
            double mean = (double)total * (1.0 / (double)FX_SCALE) * (1.0 / (double)BATCH);
            out[0] = (float)mean;
            atomicExch(&g_acc, 0ULL);   // reset for next graph replay
        }
    }
}

extern "C" void kernel_launch(void* const* d_in, const int* in_sizes, int n_in,
                              void* d_out, int out_size)
{
    // Identify inputs by UNIQUE element counts (order-proof):
    //   x: 131072, labels: 256, centers: 43899904
    const float* x = nullptr;
    const int*   labels_i32 = nullptr;
    const float* centers = nullptr;

    for (int i = 0; i < n_in; ++i) {
        if (in_sizes[i] == BATCH * FEAT_DIM)   x = (const float*)d_in[i];
        else if (in_sizes[i] == BATCH)         labels_i32 = (const int*)d_in[i];
        else                                   centers = (const float*)d_in[i];
    }

    center_loss_onepass_kernel<<<BATCH / 8, 256>>>(x, labels_i32, centers, (float*)d_out);
}